// round 9
// baseline (speedup 1.0000x reference)
#include <cuda_runtime.h>
#include <cuda_fp16.h>
#include <cstdint>
#include <math.h>

#define Bc 4
#define Sq 1024
#define Dm 1024
#define Hh 16
#define DHd 64

// ---------------- device scratch (allocation-free rule) ----------------
static constexpr size_t NNqkv = (size_t)Bc * Hh * Sq * DHd;
__device__ __half g_Qh[NNqkv], g_Ql[NNqkv];   // Q split hi/lo, pre-scaled by 1/8
__device__ __half g_Kx[NNqkv];                // K single fp16
__device__ __half g_Vx[NNqkv];                // V single fp16

__device__ __half g_xh[4096*1024], g_xl[4096*1024];   // x split [m][k]
__device__ __half g_w1x[3072*1024];                   // w1^T single [n][k]
__device__ __half g_w2x[1024*1024];                   // w2^T single [n][k]
__device__ __half g_ah[4096*1024], g_al[4096*1024];   // attn out split [m][k]

// ---------------- helpers ----------------
__device__ __forceinline__ uint32_t smem_u32(const void* p) {
    uint32_t a;
    asm("{ .reg .u64 t; cvta.to.shared.u64 t, %1; cvt.u32.u64 %0, t; }" : "=r"(a) : "l"(p));
    return a;
}
__device__ __forceinline__ void cp_async16(uint32_t saddr, const void* gaddr) {
    asm volatile("cp.async.cg.shared.global [%0], [%1], 16;" :: "r"(saddr), "l"(gaddr));
}
__device__ __forceinline__ void cp_commit() { asm volatile("cp.async.commit_group;" ::: "memory"); }
__device__ __forceinline__ void cp_wait1()  { asm volatile("cp.async.wait_group 1;"  ::: "memory"); }
__device__ __forceinline__ void cp_wait0()  { asm volatile("cp.async.wait_group 0;"  ::: "memory"); }

__device__ __forceinline__ void ldm_x4(uint32_t* r, uint32_t addr) {
    asm volatile("ldmatrix.sync.aligned.m8n8.x4.shared.b16 {%0,%1,%2,%3}, [%4];"
        : "=r"(r[0]), "=r"(r[1]), "=r"(r[2]), "=r"(r[3]) : "r"(addr));
}
__device__ __forceinline__ void ldm_x4_t(uint32_t* r, uint32_t addr) {
    asm volatile("ldmatrix.sync.aligned.m8n8.x4.trans.shared.b16 {%0,%1,%2,%3}, [%4];"
        : "=r"(r[0]), "=r"(r[1]), "=r"(r[2]), "=r"(r[3]) : "r"(addr));
}
// fp32-accumulate HMMA (hi pass)
__device__ __forceinline__ void mma16816(float* d, const uint32_t* a, const uint32_t* b) {
    asm volatile("mma.sync.aligned.m16n8k16.row.col.f32.f16.f16.f32 "
        "{%0,%1,%2,%3}, {%4,%5,%6,%7}, {%8,%9}, {%0,%1,%2,%3};"
        : "+f"(d[0]), "+f"(d[1]), "+f"(d[2]), "+f"(d[3])
        : "r"(a[0]), "r"(a[1]), "r"(a[2]), "r"(a[3]), "r"(b[0]), "r"(b[1]));
}
// fp16-accumulate HMMA (lo-correction pass; candidate 2x rate)
__device__ __forceinline__ void mma16816_h(uint32_t* d, const uint32_t* a, const uint32_t* b) {
    asm volatile("mma.sync.aligned.m16n8k16.row.col.f16.f16.f16.f16 "
        "{%0,%1}, {%2,%3,%4,%5}, {%6,%7}, {%0,%1};"
        : "+r"(d[0]), "+r"(d[1])
        : "r"(a[0]), "r"(a[1]), "r"(a[2]), "r"(a[3]), "r"(b[0]), "r"(b[1]));
}
__device__ __forceinline__ void addh2(float* acc4, const uint32_t* d2) {
    float2 p0 = __half22float2(*(const __half2*)&d2[0]);
    float2 p1 = __half22float2(*(const __half2*)&d2[1]);
    acc4[0] += p0.x; acc4[1] += p0.y; acc4[2] += p1.x; acc4[3] += p1.y;
}
__device__ __forceinline__ uint32_t swz(uint32_t off) { return off ^ ((off >> 3) & 0x70); }

__device__ __forceinline__ void pack_hl(float a, float b, uint32_t& hi, uint32_t& lo) {
    __half2 hh = __floats2half2_rn(a, b);
    float ra = a - __half2float(__low2half(hh));
    float rb = b - __half2float(__high2half(hh));
    __half2 ll = __floats2half2_rn(ra, rb);
    hi = *reinterpret_cast<uint32_t*>(&hh);
    lo = *reinterpret_cast<uint32_t*>(&ll);
}
__device__ __forceinline__ uint32_t pack_h2(float a, float b) {
    __half2 hh = __floats2half2_rn(a, b);
    return *reinterpret_cast<uint32_t*>(&hh);
}

// ---------------- split conversion kernels ----------------
__global__ void split_k(const float* __restrict__ in, int n)
{
    int base = (blockIdx.x * blockDim.x + threadIdx.x) * 4;
    if (base >= n) return;
    float4 v = *(const float4*)(in + base);
    uint32_t h0, l0, h1, l1;
    pack_hl(v.x, v.y, h0, l0);
    pack_hl(v.z, v.w, h1, l1);
    *(uint32_t*)(g_xh + base)     = h0;
    *(uint32_t*)(g_xh + base + 2) = h1;
    *(uint32_t*)(g_xl + base)     = l0;
    *(uint32_t*)(g_xl + base + 2) = l1;
}

template<int W>
__global__ void tsplit_k(const float* __restrict__ w)
{
    const int K = 1024;
    const int N = (W == 1) ? 3072 : 1024;
    __half* th = (W == 1) ? g_w1x : g_w2x;
    __shared__ float t[32][33];
    int n0 = blockIdx.x * 32, k0 = blockIdx.y * 32;
    int tx = threadIdx.x, ty = threadIdx.y;
    #pragma unroll
    for (int i = 0; i < 32; i += 8)
        t[ty + i][tx] = w[(size_t)(k0 + ty + i) * N + n0 + tx];
    __syncthreads();
    #pragma unroll
    for (int i = 0; i < 32; i += 8)
        th[(size_t)(n0 + ty + i) * K + k0 + tx] = __float2half_rn(t[tx][ty + i]);
}

// ---------------- HMMA fp16 hi(f32acc)+lo(f16acc) GEMM ----------------
// 256x128 tile, 256 threads, warp 64x64.
// Stage: Ah[0,32K) Al[32K,64K) B[64K,80K); 2 stages = 160KB.
static constexpr int ST2_BYTES   = 81920;
static constexpr int SMEM_TOTAL2 = 2 * ST2_BYTES;

__device__ __forceinline__ void load_stage2(uint32_t sbase,
                                            const __half* Ah, const __half* Al,
                                            const __half* B,
                                            int mBase, int nBase, int K, int k0, int tid)
{
    const char* gah = (const char*)(Ah + (size_t)mBase * K + k0);
    const char* gal = (const char*)(Al + (size_t)mBase * K + k0);
    #pragma unroll
    for (int i = 0; i < 8; i++) {
        int id = tid + i * 256;
        int r  = id >> 3;
        int cb = (id & 7) * 16;
        uint32_t off = swz((uint32_t)(r * 128 + cb));
        cp_async16(sbase + off,         gah + (size_t)r * K * 2 + cb);
        cp_async16(sbase + 32768 + off, gal + (size_t)r * K * 2 + cb);
    }
    const char* gb = (const char*)(B + (size_t)nBase * K + k0);
    #pragma unroll
    for (int i = 0; i < 4; i++) {
        int id = tid + i * 256;
        int r  = id >> 3;
        int cb = (id & 7) * 16;
        cp_async16(sbase + 65536 + swz((uint32_t)(r * 128 + cb)), gb + (size_t)r * K * 2 + cb);
    }
}

template<int MODE>   // 1 = QKV scatter, 0 = proj store fp32
__global__ __launch_bounds__(256, 1) void tgemm(const float* __restrict__ bias,
                                                float* __restrict__ C)
{
    const int K = 1024;
    const int N = (MODE == 1) ? 3072 : 1024;
    const __half* Ah = (MODE == 1) ? g_xh : g_ah;
    const __half* Al = (MODE == 1) ? g_xl : g_al;
    const __half* B  = (MODE == 1) ? g_w1x : g_w2x;

    extern __shared__ char smem[];
    uint32_t sb = smem_u32(smem);
    int tid = threadIdx.x;
    int wid = tid >> 5, l = tid & 31;
    int M0 = (wid & 3) * 64;
    int N0 = (wid >> 2) * 64;
    int mBase = blockIdx.y * 256, nBase = blockIdx.x * 128;

    float acc[4][8][4];
    #pragma unroll
    for (int mi = 0; mi < 4; mi++)
        #pragma unroll
        for (int nj = 0; nj < 8; nj++)
            #pragma unroll
            for (int k = 0; k < 4; k++) acc[mi][nj][k] = 0.f;

    int aRow = (l & 7) + ((l >> 3) & 1) * 8;
    int aCb  = ((l >> 4) & 1) * 16;
    int bRow = (l & 7) + ((l >> 4) & 1) * 8;
    int bCb  = ((l >> 3) & 1) * 16;

    const int NK = K / 64;
    load_stage2(sb,             Ah, Al, B, mBase, nBase, K, 0,  tid); cp_commit();
    load_stage2(sb + ST2_BYTES, Ah, Al, B, mBase, nBase, K, 64, tid); cp_commit();

    for (int ko = 0; ko < NK; ko++) {
        cp_wait1();
        __syncthreads();
        uint32_t stage = sb + (ko & 1) * ST2_BYTES;

        #pragma unroll
        for (int ks = 0; ks < 4; ks++) {
            uint32_t rah[4][4], ral[4][4], rb[4][4];
            #pragma unroll
            for (int mi = 0; mi < 4; mi++) {
                uint32_t aoff = swz((uint32_t)((M0 + mi*16 + aRow) * 128 + ks*32 + aCb));
                ldm_x4(rah[mi], stage + aoff);
                ldm_x4(ral[mi], stage + 32768 + aoff);
            }
            #pragma unroll
            for (int nq = 0; nq < 4; nq++)
                ldm_x4(rb[nq], stage + 65536 + swz((uint32_t)((N0 + nq*16 + bRow) * 128 + ks*32 + bCb)));
            #pragma unroll
            for (int mi = 0; mi < 4; mi++) {
                uint32_t lo[8][2];
                #pragma unroll
                for (int nj = 0; nj < 8; nj++) {
                    const uint32_t* bp = &rb[nj >> 1][(nj & 1) * 2];
                    mma16816(acc[mi][nj], rah[mi], bp);       // hi: f32 acc
                    lo[nj][0] = 0u; lo[nj][1] = 0u;
                    mma16816_h(lo[nj], ral[mi], bp);          // lo: f16 acc
                }
                #pragma unroll
                for (int nj = 0; nj < 8; nj++)
                    addh2(acc[mi][nj], lo[nj]);
            }
        }
        __syncthreads();
        if (ko + 2 < NK)
            load_stage2(sb + (ko & 1) * ST2_BYTES, Ah, Al, B, mBase, nBase, K, (ko + 2) * 64, tid);
        cp_commit();
    }

    #pragma unroll
    for (int mi = 0; mi < 4; mi++) {
        #pragma unroll
        for (int half = 0; half < 2; half++) {
            int m = mBase + M0 + mi * 16 + (l >> 2) + half * 8;
            #pragma unroll
            for (int nj = 0; nj < 8; nj++) {
                int n = nBase + N0 + nj * 8 + (l & 3) * 2;
                float v0 = acc[mi][nj][half * 2 + 0] + bias[n];
                float v1 = acc[mi][nj][half * 2 + 1] + bias[n + 1];
                if (MODE == 1) {
                    int which = n >> 10;
                    int dc = n & 1023;
                    int h = dc >> 6, dh = dc & 63;
                    int b = m >> 10, s2 = m & 1023;
                    size_t gi = (((size_t)(b * Hh + h)) * Sq + s2) * DHd + dh;
                    if (which == 0) {
                        uint32_t hh, ll;
                        pack_hl(v0 * 0.125f, v1 * 0.125f, hh, ll);
                        *(uint32_t*)&g_Qh[gi] = hh;
                        *(uint32_t*)&g_Ql[gi] = ll;
                    } else if (which == 1) {
                        *(uint32_t*)&g_Kx[gi] = pack_h2(v0, v1);
                    } else {
                        *(uint32_t*)&g_Vx[gi] = pack_h2(v0, v1);
                    }
                } else {
                    C[(size_t)m * N + n]     = v0;
                    C[(size_t)m * N + n + 1] = v1;
                }
            }
        }
    }
}

// ---------------- tensor-core causal flash attention ----------------
// SMEM: Qh[0,16K) Ql[16K,32K); stages at 32K: {K 8K, V 8K} x 2. Total 64K.
static constexpr int FL_SMEM = 32768 + 2 * 16384;

__device__ __forceinline__ void load_kv(uint32_t sdst, int bh, int kt, int tid)
{
    const __half* srcs[2] = {g_Kx, g_Vx};
    size_t base = (size_t)bh * Sq * DHd + (size_t)kt * 64 * DHd;
    #pragma unroll
    for (int t = 0; t < 2; t++) {
        const char* g = (const char*)(srcs[t] + base);
        uint32_t sd = sdst + t * 8192;
        #pragma unroll
        for (int i = 0; i < 2; i++) {
            int id = tid + i * 256;
            int r  = id >> 3;
            int cb = (id & 7) * 16;
            cp_async16(sd + swz((uint32_t)(r * 128 + cb)), g + (size_t)r * 128 + cb);
        }
    }
}

__global__ __launch_bounds__(256) void flash_mma()
{
    extern __shared__ char smem[];
    uint32_t sb = smem_u32(smem);
    int tid = threadIdx.x;
    int w = tid >> 5, l = tid & 31;

    int qc = 7 - (blockIdx.x >> 6);
    int bh = blockIdx.x & 63;
    int qBase = qc * 128;

    {
        const char* gh = (const char*)(g_Qh + (size_t)bh * Sq * DHd + (size_t)qBase * DHd);
        const char* gl = (const char*)(g_Ql + (size_t)bh * Sq * DHd + (size_t)qBase * DHd);
        #pragma unroll
        for (int i = 0; i < 4; i++) {
            int id = tid + i * 256;
            int r  = id >> 3;
            int cb = (id & 7) * 16;
            cp_async16(sb +         swz((uint32_t)(r * 128 + cb)), gh + (size_t)r * 128 + cb);
            cp_async16(sb + 16384 + swz((uint32_t)(r * 128 + cb)), gl + (size_t)r * 128 + cb);
        }
    }
    load_kv(sb + 32768, bh, 0, tid);
    cp_commit();
    int nT = (qc + 1) * 2;
    load_kv(sb + 32768 + 16384, bh, 1, tid);
    cp_commit();

    cp_wait1();
    __syncthreads();

    int aRow = (l & 7) + ((l >> 3) & 1) * 8;
    int aCb  = ((l >> 4) & 1) * 16;
    int bRow = (l & 7) + ((l >> 4) & 1) * 8;
    int bCb  = ((l >> 3) & 1) * 16;
    int vRow = (l & 7) + ((l >> 3) & 1) * 8;
    int vCb  = ((l >> 4) & 1) * 16;

    uint32_t qh[4][4], ql[4][4];
    #pragma unroll
    for (int ks = 0; ks < 4; ks++) {
        ldm_x4(qh[ks], sb +         swz((uint32_t)((w*16 + aRow) * 128 + ks*32 + aCb)));
        ldm_x4(ql[ks], sb + 16384 + swz((uint32_t)((w*16 + aRow) * 128 + ks*32 + aCb)));
    }

    float o[8][4];
    #pragma unroll
    for (int nj = 0; nj < 8; nj++)
        #pragma unroll
        for (int k = 0; k < 4; k++) o[nj][k] = 0.f;
    float m0 = -1e30f, m1 = -1e30f, l0 = 0.f, l1 = 0.f;

    for (int kt = 0; kt < nT; kt++) {
        cp_wait1();
        __syncthreads();
        uint32_t stage = sb + 32768 + (kt & 1) * 16384;

        bool skip = (kt * 64 > qBase + w * 16 + 15);
        if (!skip) {
            float sacc[8][4];
            #pragma unroll
            for (int nj = 0; nj < 8; nj++)
                #pragma unroll
                for (int k = 0; k < 4; k++) sacc[nj][k] = 0.f;

            #pragma unroll
            for (int ks = 0; ks < 4; ks++) {
                #pragma unroll
                for (int nq = 0; nq < 4; nq++) {
                    uint32_t kh4[4];
                    ldm_x4(kh4, stage + swz((uint32_t)((nq*16 + bRow) * 128 + ks*32 + bCb)));
                    mma16816(sacc[2*nq],   qh[ks], &kh4[0]);
                    mma16816(sacc[2*nq+1], qh[ks], &kh4[2]);
                    uint32_t lo0[2] = {0u, 0u}, lo1[2] = {0u, 0u};
                    mma16816_h(lo0, ql[ks], &kh4[0]);
                    mma16816_h(lo1, ql[ks], &kh4[2]);
                    addh2(sacc[2*nq],   lo0);
                    addh2(sacc[2*nq+1], lo1);
                }
            }

            int r0 = qBase + w * 16 + (l >> 2);
            if (kt * 64 + 63 > r0) {
                int kc = kt * 64 + (l & 3) * 2;
                #pragma unroll
                for (int nj = 0; nj < 8; nj++) {
                    int k0 = kc + nj * 8;
                    if (k0     > r0)     sacc[nj][0] = -1e30f;
                    if (k0 + 1 > r0)     sacc[nj][1] = -1e30f;
                    if (k0     > r0 + 8) sacc[nj][2] = -1e30f;
                    if (k0 + 1 > r0 + 8) sacc[nj][3] = -1e30f;
                }
            }

            float mx0 = -1e30f, mx1 = -1e30f;
            #pragma unroll
            for (int nj = 0; nj < 8; nj++) {
                mx0 = fmaxf(mx0, fmaxf(sacc[nj][0], sacc[nj][1]));
                mx1 = fmaxf(mx1, fmaxf(sacc[nj][2], sacc[nj][3]));
            }
            mx0 = fmaxf(mx0, __shfl_xor_sync(0xffffffffu, mx0, 1));
            mx0 = fmaxf(mx0, __shfl_xor_sync(0xffffffffu, mx0, 2));
            mx1 = fmaxf(mx1, __shfl_xor_sync(0xffffffffu, mx1, 1));
            mx1 = fmaxf(mx1, __shfl_xor_sync(0xffffffffu, mx1, 2));
            float mn0 = fmaxf(m0, mx0), mn1 = fmaxf(m1, mx1);
            float sc0 = __expf(m0 - mn0), sc1 = __expf(m1 - mn1);
            l0 *= sc0; l1 *= sc1;
            #pragma unroll
            for (int nj = 0; nj < 8; nj++) {
                o[nj][0] *= sc0; o[nj][1] *= sc0;
                o[nj][2] *= sc1; o[nj][3] *= sc1;
            }
            #pragma unroll
            for (int nj = 0; nj < 8; nj++) {
                sacc[nj][0] = __expf(sacc[nj][0] - mn0); l0 += sacc[nj][0];
                sacc[nj][1] = __expf(sacc[nj][1] - mn0); l0 += sacc[nj][1];
                sacc[nj][2] = __expf(sacc[nj][2] - mn1); l1 += sacc[nj][2];
                sacc[nj][3] = __expf(sacc[nj][3] - mn1); l1 += sacc[nj][3];
            }
            m0 = mn0; m1 = mn1;

            uint32_t pah[4][4], pal[4][4];
            #pragma unroll
            for (int ks = 0; ks < 4; ks++) {
                pack_hl(sacc[2*ks][0],   sacc[2*ks][1],   pah[ks][0], pal[ks][0]);
                pack_hl(sacc[2*ks][2],   sacc[2*ks][3],   pah[ks][1], pal[ks][1]);
                pack_hl(sacc[2*ks+1][0], sacc[2*ks+1][1], pah[ks][2], pal[ks][2]);
                pack_hl(sacc[2*ks+1][2], sacc[2*ks+1][3], pah[ks][3], pal[ks][3]);
            }

            uint32_t vStage = stage + 8192;
            #pragma unroll
            for (int ks = 0; ks < 4; ks++) {
                #pragma unroll
                for (int nq = 0; nq < 4; nq++) {
                    uint32_t vh4[4];
                    ldm_x4_t(vh4, vStage + swz((uint32_t)((ks*16 + vRow) * 128 + nq*32 + vCb)));
                    mma16816(o[2*nq],   pah[ks], &vh4[0]);
                    mma16816(o[2*nq+1], pah[ks], &vh4[2]);
                    uint32_t lo0[2] = {0u, 0u}, lo1[2] = {0u, 0u};
                    mma16816_h(lo0, pal[ks], &vh4[0]);
                    mma16816_h(lo1, pal[ks], &vh4[2]);
                    addh2(o[2*nq],   lo0);
                    addh2(o[2*nq+1], lo1);
                }
            }
        }

        __syncthreads();
        if (kt + 2 < nT) load_kv(sb + 32768 + (kt & 1) * 16384, bh, kt + 2, tid);
        cp_commit();
    }
    cp_wait0();

    l0 += __shfl_xor_sync(0xffffffffu, l0, 1);
    l0 += __shfl_xor_sync(0xffffffffu, l0, 2);
    l1 += __shfl_xor_sync(0xffffffffu, l1, 1);
    l1 += __shfl_xor_sync(0xffffffffu, l1, 2);
    float inv0 = 1.f / l0, inv1 = 1.f / l1;

    int b = bh >> 4, h = bh & 15;
    int row0 = qBase + w * 16 + (l >> 2);
    #pragma unroll
    for (int half = 0; half < 2; half++) {
        int row = row0 + half * 8;
        float inv = half ? inv1 : inv0;
        #pragma unroll
        for (int nj = 0; nj < 8; nj++) {
            int col = h * 64 + nj * 8 + (l & 3) * 2;
            float v0 = o[nj][half * 2 + 0] * inv;
            float v1 = o[nj][half * 2 + 1] * inv;
            uint32_t hh, ll;
            pack_hl(v0, v1, hh, ll);
            size_t gi = (size_t)(b * Sq + row) * Dm + col;
            *(uint32_t*)&g_ah[gi] = hh;
            *(uint32_t*)&g_al[gi] = ll;
        }
    }
}

// ---------------------------------------------------------------------------
extern "C" void kernel_launch(void* const* d_in, const int* in_sizes, int n_in,
                              void* d_out, int out_size)
{
    (void)in_sizes; (void)n_in; (void)out_size;
    const float* x  = (const float*)d_in[0];
    const float* w1 = (const float*)d_in[1];
    const float* b1 = (const float*)d_in[2];
    const float* w2 = (const float*)d_in[3];
    const float* b2 = (const float*)d_in[4];
    float* out = (float*)d_out;

    cudaFuncSetAttribute(tgemm<1>, cudaFuncAttributeMaxDynamicSharedMemorySize, SMEM_TOTAL2);
    cudaFuncSetAttribute(tgemm<0>, cudaFuncAttributeMaxDynamicSharedMemorySize, SMEM_TOTAL2);
    cudaFuncSetAttribute(flash_mma, cudaFuncAttributeMaxDynamicSharedMemorySize, FL_SMEM);

    split_k<<<4096, 256>>>(x, 4096 * 1024);
    tsplit_k<1><<<dim3(3072 / 32, 1024 / 32), dim3(32, 8)>>>(w1);
    tsplit_k<2><<<dim3(1024 / 32, 1024 / 32), dim3(32, 8)>>>(w2);

    tgemm<1><<<dim3(3072 / 128, 4096 / 256), 256, SMEM_TOTAL2>>>(b1, nullptr);
    flash_mma<<<512, 256, FL_SMEM>>>();
    tgemm<0><<<dim3(1024 / 128, 4096 / 256), 256, SMEM_TOTAL2>>>(b2, out);
}

// round 10
// speedup vs baseline: 1.3159x; 1.3159x over previous
#include <cuda_runtime.h>
#include <cuda_fp16.h>
#include <cstdint>
#include <math.h>

#define Bc 4
#define Sq 1024
#define Dm 1024
#define Hh 16
#define DHd 64

// ---------------- device scratch (allocation-free rule) ----------------
static constexpr size_t NNqkv = (size_t)Bc * Hh * Sq * DHd;
__device__ __half g_Qh[NNqkv], g_Ql[NNqkv];   // Q split hi/lo, pre-scaled by 1/8
__device__ __half g_Kx[NNqkv];                // K single fp16
__device__ __half g_Vx[NNqkv];                // V single fp16

__device__ __half g_xh[4096*1024], g_xl[4096*1024];   // x split [m][k]
__device__ __half g_w1x[3072*1024];                   // w1^T single [n][k]
__device__ __half g_w2x[1024*1024];                   // w2^T single [n][k]
__device__ __half g_ah[4096*1024], g_al[4096*1024];   // attn out split [m][k]

// ---------------- helpers ----------------
__device__ __forceinline__ uint32_t smem_u32(const void* p) {
    uint32_t a;
    asm("{ .reg .u64 t; cvta.to.shared.u64 t, %1; cvt.u32.u64 %0, t; }" : "=r"(a) : "l"(p));
    return a;
}
__device__ __forceinline__ void cp_async16(uint32_t saddr, const void* gaddr) {
    asm volatile("cp.async.cg.shared.global [%0], [%1], 16;" :: "r"(saddr), "l"(gaddr));
}
__device__ __forceinline__ void cp_commit() { asm volatile("cp.async.commit_group;" ::: "memory"); }
__device__ __forceinline__ void cp_wait1()  { asm volatile("cp.async.wait_group 1;"  ::: "memory"); }
__device__ __forceinline__ void cp_wait2()  { asm volatile("cp.async.wait_group 2;"  ::: "memory"); }
__device__ __forceinline__ void cp_wait0()  { asm volatile("cp.async.wait_group 0;"  ::: "memory"); }

__device__ __forceinline__ void ldm_x4(uint32_t* r, uint32_t addr) {
    asm volatile("ldmatrix.sync.aligned.m8n8.x4.shared.b16 {%0,%1,%2,%3}, [%4];"
        : "=r"(r[0]), "=r"(r[1]), "=r"(r[2]), "=r"(r[3]) : "r"(addr));
}
__device__ __forceinline__ void ldm_x4_t(uint32_t* r, uint32_t addr) {
    asm volatile("ldmatrix.sync.aligned.m8n8.x4.trans.shared.b16 {%0,%1,%2,%3}, [%4];"
        : "=r"(r[0]), "=r"(r[1]), "=r"(r[2]), "=r"(r[3]) : "r"(addr));
}
__device__ __forceinline__ void mma16816(float* d, const uint32_t* a, const uint32_t* b) {
    asm volatile("mma.sync.aligned.m16n8k16.row.col.f32.f16.f16.f32 "
        "{%0,%1,%2,%3}, {%4,%5,%6,%7}, {%8,%9}, {%0,%1,%2,%3};"
        : "+f"(d[0]), "+f"(d[1]), "+f"(d[2]), "+f"(d[3])
        : "r"(a[0]), "r"(a[1]), "r"(a[2]), "r"(a[3]), "r"(b[0]), "r"(b[1]));
}
__device__ __forceinline__ uint32_t swz(uint32_t off)   { return off ^ ((off >> 3) & 0x70); }  // 128B rows
__device__ __forceinline__ uint32_t swz64(uint32_t off) { return off ^ ((off >> 3) & 0x30); }  // 64B rows

__device__ __forceinline__ void pack_hl(float a, float b, uint32_t& hi, uint32_t& lo) {
    __half2 hh = __floats2half2_rn(a, b);
    float ra = a - __half2float(__low2half(hh));
    float rb = b - __half2float(__high2half(hh));
    __half2 ll = __floats2half2_rn(ra, rb);
    hi = *reinterpret_cast<uint32_t*>(&hh);
    lo = *reinterpret_cast<uint32_t*>(&ll);
}
__device__ __forceinline__ uint32_t pack_h2(float a, float b) {
    __half2 hh = __floats2half2_rn(a, b);
    return *reinterpret_cast<uint32_t*>(&hh);
}

// ---------------- split conversion kernels ----------------
__global__ void split_k(const float* __restrict__ in, int n)
{
    int base = (blockIdx.x * blockDim.x + threadIdx.x) * 4;
    if (base >= n) return;
    float4 v = *(const float4*)(in + base);
    uint32_t h0, l0, h1, l1;
    pack_hl(v.x, v.y, h0, l0);
    pack_hl(v.z, v.w, h1, l1);
    *(uint32_t*)(g_xh + base)     = h0;
    *(uint32_t*)(g_xh + base + 2) = h1;
    *(uint32_t*)(g_xl + base)     = l0;
    *(uint32_t*)(g_xl + base + 2) = l1;
}

template<int W>
__global__ void tsplit_k(const float* __restrict__ w)
{
    const int K = 1024;
    const int N = (W == 1) ? 3072 : 1024;
    __half* th = (W == 1) ? g_w1x : g_w2x;
    __shared__ float t[32][33];
    int n0 = blockIdx.x * 32, k0 = blockIdx.y * 32;
    int tx = threadIdx.x, ty = threadIdx.y;
    #pragma unroll
    for (int i = 0; i < 32; i += 8)
        t[ty + i][tx] = w[(size_t)(k0 + ty + i) * N + n0 + tx];
    __syncthreads();
    #pragma unroll
    for (int i = 0; i < 32; i += 8)
        th[(size_t)(n0 + ty + i) * K + k0 + tx] = __float2half_rn(t[tx][ty + i]);
}

// ---------------- HMMA fp16 hi(+lo) GEMM, 256x128 tile, 256 thr, warp 64x64 --
// BK=32, 4 stages. Stage: Ah[0,16K) Al[16K,32K) B[32K,40K). Total 160KB.
static constexpr int TG_STAGES  = 4;
static constexpr int STG_BYTES  = 40960;
static constexpr int SMEM_TG    = TG_STAGES * STG_BYTES;   // 163840

__device__ __forceinline__ void load_stage32(uint32_t sbase,
                                             const __half* Ah, const __half* Al,
                                             const __half* B, bool do_lo,
                                             int mBase, int nBase, int K, int k0, int tid)
{
    const char* gah = (const char*)(Ah + (size_t)mBase * K + k0);
    const char* gal = (const char*)(Al + (size_t)mBase * K + k0);
    #pragma unroll
    for (int i = 0; i < 4; i++) {
        int id = tid + i * 256;          // 0..1023 -> 256 rows x 4 chunks
        int r  = id >> 2;
        int cb = (id & 3) * 16;
        uint32_t off = swz64((uint32_t)(r * 64 + cb));
        cp_async16(sbase + off, gah + (size_t)r * K * 2 + cb);
        if (do_lo)
            cp_async16(sbase + 16384 + off, gal + (size_t)r * K * 2 + cb);
    }
    const char* gb = (const char*)(B + (size_t)nBase * K + k0);
    #pragma unroll
    for (int i = 0; i < 2; i++) {
        int id = tid + i * 256;          // 0..511 -> 128 rows x 4 chunks
        int r  = id >> 2;
        int cb = (id & 3) * 16;
        cp_async16(sbase + 32768 + swz64((uint32_t)(r * 64 + cb)), gb + (size_t)r * K * 2 + cb);
    }
}

template<int MODE>   // 1 = QKV scatter, 0 = proj store fp32
__global__ __launch_bounds__(256, 1) void tgemm(const float* __restrict__ bias,
                                                float* __restrict__ C)
{
    const int K = 1024;
    const int N = (MODE == 1) ? 3072 : 1024;
    const __half* Ah = (MODE == 1) ? g_xh : g_ah;
    const __half* Al = (MODE == 1) ? g_xl : g_al;
    const __half* B  = (MODE == 1) ? g_w1x : g_w2x;

    extern __shared__ char smem[];
    uint32_t sb = smem_u32(smem);
    int tid = threadIdx.x;
    int wid = tid >> 5, l = tid & 31;
    int M0 = (wid & 3) * 64;
    int N0 = (wid >> 2) * 64;
    int mBase = blockIdx.y * 256, nBase = blockIdx.x * 128;
    // lo-correction needed only where the result is kept at high precision:
    // Q columns (n<1024) in QKV mode; everywhere in proj mode.
    bool do_lo = (MODE == 0) || (nBase < 1024);

    float acc[4][8][4];
    #pragma unroll
    for (int mi = 0; mi < 4; mi++)
        #pragma unroll
        for (int nj = 0; nj < 8; nj++)
            #pragma unroll
            for (int k = 0; k < 4; k++) acc[mi][nj][k] = 0.f;

    int aRow = (l & 7) + ((l >> 3) & 1) * 8;
    int aCb  = ((l >> 4) & 1) * 16;
    int bRow = (l & 7) + ((l >> 4) & 1) * 8;
    int bCb  = ((l >> 3) & 1) * 16;

    const int NK = K / 32;   // 32
    #pragma unroll
    for (int s = 0; s < 3; s++) {
        load_stage32(sb + s * STG_BYTES, Ah, Al, B, do_lo, mBase, nBase, K, s * 32, tid);
        cp_commit();
    }

    for (int ko = 0; ko < NK; ko++) {
        cp_wait2();
        __syncthreads();
        uint32_t stage = sb + (ko & (TG_STAGES - 1)) * STG_BYTES;

        #pragma unroll
        for (int ks = 0; ks < 2; ks++) {
            uint32_t rah[4][4], ral[4][4], rb[4][4];
            #pragma unroll
            for (int mi = 0; mi < 4; mi++) {
                uint32_t aoff = swz64((uint32_t)((M0 + mi*16 + aRow) * 64 + ks*32 + aCb));
                ldm_x4(rah[mi], stage + aoff);
                if (do_lo) ldm_x4(ral[mi], stage + 16384 + aoff);
            }
            #pragma unroll
            for (int nq = 0; nq < 4; nq++)
                ldm_x4(rb[nq], stage + 32768 + swz64((uint32_t)((N0 + nq*16 + bRow) * 64 + ks*32 + bCb)));
            #pragma unroll
            for (int mi = 0; mi < 4; mi++)
                #pragma unroll
                for (int nj = 0; nj < 8; nj++) {
                    const uint32_t* bp = &rb[nj >> 1][(nj & 1) * 2];
                    mma16816(acc[mi][nj], rah[mi], bp);
                    if (do_lo) mma16816(acc[mi][nj], ral[mi], bp);
                }
        }
        // issue next stage (writes stage (ko-1)%4, consumed last iter; safe after top sync)
        if (ko + 3 < NK)
            load_stage32(sb + ((ko + 3) & (TG_STAGES - 1)) * STG_BYTES,
                         Ah, Al, B, do_lo, mBase, nBase, K, (ko + 3) * 32, tid);
        cp_commit();   // unconditional: keeps group count aligned with wait_group(2)
    }

    #pragma unroll
    for (int mi = 0; mi < 4; mi++) {
        #pragma unroll
        for (int half = 0; half < 2; half++) {
            int m = mBase + M0 + mi * 16 + (l >> 2) + half * 8;
            #pragma unroll
            for (int nj = 0; nj < 8; nj++) {
                int n = nBase + N0 + nj * 8 + (l & 3) * 2;
                float v0 = acc[mi][nj][half * 2 + 0] + bias[n];
                float v1 = acc[mi][nj][half * 2 + 1] + bias[n + 1];
                if (MODE == 1) {
                    int which = n >> 10;
                    int dc = n & 1023;
                    int h = dc >> 6, dh = dc & 63;
                    int b = m >> 10, s2 = m & 1023;
                    size_t gi = (((size_t)(b * Hh + h)) * Sq + s2) * DHd + dh;
                    if (which == 0) {
                        uint32_t hh, ll;
                        pack_hl(v0 * 0.125f, v1 * 0.125f, hh, ll);
                        *(uint32_t*)&g_Qh[gi] = hh;
                        *(uint32_t*)&g_Ql[gi] = ll;
                    } else if (which == 1) {
                        *(uint32_t*)&g_Kx[gi] = pack_h2(v0, v1);
                    } else {
                        *(uint32_t*)&g_Vx[gi] = pack_h2(v0, v1);
                    }
                } else {
                    C[(size_t)m * N + n]     = v0;
                    C[(size_t)m * N + n + 1] = v1;
                }
            }
        }
    }
}

// ---------------- tensor-core causal flash attention (R8 version) ----------------
// SMEM: Qh[0,16K) Ql[16K,32K); stages at 32K: {K 8K, V 8K} x 2. Total 64K.
static constexpr int FL_SMEM = 32768 + 2 * 16384;

__device__ __forceinline__ void load_kv(uint32_t sdst, int bh, int kt, int tid)
{
    const __half* srcs[2] = {g_Kx, g_Vx};
    size_t base = (size_t)bh * Sq * DHd + (size_t)kt * 64 * DHd;
    #pragma unroll
    for (int t = 0; t < 2; t++) {
        const char* g = (const char*)(srcs[t] + base);
        uint32_t sd = sdst + t * 8192;
        #pragma unroll
        for (int i = 0; i < 2; i++) {
            int id = tid + i * 256;
            int r  = id >> 3;
            int cb = (id & 7) * 16;
            cp_async16(sd + swz((uint32_t)(r * 128 + cb)), g + (size_t)r * 128 + cb);
        }
    }
}

__global__ __launch_bounds__(256) void flash_mma()
{
    extern __shared__ char smem[];
    uint32_t sb = smem_u32(smem);
    int tid = threadIdx.x;
    int w = tid >> 5, l = tid & 31;

    int qc = 7 - (blockIdx.x >> 6);
    int bh = blockIdx.x & 63;
    int qBase = qc * 128;

    {
        const char* gh = (const char*)(g_Qh + (size_t)bh * Sq * DHd + (size_t)qBase * DHd);
        const char* gl = (const char*)(g_Ql + (size_t)bh * Sq * DHd + (size_t)qBase * DHd);
        #pragma unroll
        for (int i = 0; i < 4; i++) {
            int id = tid + i * 256;
            int r  = id >> 3;
            int cb = (id & 7) * 16;
            cp_async16(sb +         swz((uint32_t)(r * 128 + cb)), gh + (size_t)r * 128 + cb);
            cp_async16(sb + 16384 + swz((uint32_t)(r * 128 + cb)), gl + (size_t)r * 128 + cb);
        }
    }
    load_kv(sb + 32768, bh, 0, tid);
    cp_commit();
    int nT = (qc + 1) * 2;
    load_kv(sb + 32768 + 16384, bh, 1, tid);
    cp_commit();

    cp_wait1();
    __syncthreads();

    int aRow = (l & 7) + ((l >> 3) & 1) * 8;
    int aCb  = ((l >> 4) & 1) * 16;
    int bRow = (l & 7) + ((l >> 4) & 1) * 8;
    int bCb  = ((l >> 3) & 1) * 16;
    int vRow = (l & 7) + ((l >> 3) & 1) * 8;
    int vCb  = ((l >> 4) & 1) * 16;

    uint32_t qh[4][4], ql[4][4];
    #pragma unroll
    for (int ks = 0; ks < 4; ks++) {
        ldm_x4(qh[ks], sb +         swz((uint32_t)((w*16 + aRow) * 128 + ks*32 + aCb)));
        ldm_x4(ql[ks], sb + 16384 + swz((uint32_t)((w*16 + aRow) * 128 + ks*32 + aCb)));
    }

    float o[8][4];
    #pragma unroll
    for (int nj = 0; nj < 8; nj++)
        #pragma unroll
        for (int k = 0; k < 4; k++) o[nj][k] = 0.f;
    float m0 = -1e30f, m1 = -1e30f, l0 = 0.f, l1 = 0.f;

    for (int kt = 0; kt < nT; kt++) {
        cp_wait1();
        __syncthreads();
        uint32_t stage = sb + 32768 + (kt & 1) * 16384;

        bool skip = (kt * 64 > qBase + w * 16 + 15);
        if (!skip) {
            float sacc[8][4];
            #pragma unroll
            for (int nj = 0; nj < 8; nj++)
                #pragma unroll
                for (int k = 0; k < 4; k++) sacc[nj][k] = 0.f;

            #pragma unroll
            for (int ks = 0; ks < 4; ks++) {
                #pragma unroll
                for (int nq = 0; nq < 4; nq++) {
                    uint32_t kh4[4];
                    ldm_x4(kh4, stage + swz((uint32_t)((nq*16 + bRow) * 128 + ks*32 + bCb)));
                    mma16816(sacc[2*nq],   qh[ks], &kh4[0]);
                    mma16816(sacc[2*nq+1], qh[ks], &kh4[2]);
                    mma16816(sacc[2*nq],   ql[ks], &kh4[0]);
                    mma16816(sacc[2*nq+1], ql[ks], &kh4[2]);
                }
            }

            int r0 = qBase + w * 16 + (l >> 2);
            if (kt * 64 + 63 > r0) {
                int kc = kt * 64 + (l & 3) * 2;
                #pragma unroll
                for (int nj = 0; nj < 8; nj++) {
                    int k0 = kc + nj * 8;
                    if (k0     > r0)     sacc[nj][0] = -1e30f;
                    if (k0 + 1 > r0)     sacc[nj][1] = -1e30f;
                    if (k0     > r0 + 8) sacc[nj][2] = -1e30f;
                    if (k0 + 1 > r0 + 8) sacc[nj][3] = -1e30f;
                }
            }

            float mx0 = -1e30f, mx1 = -1e30f;
            #pragma unroll
            for (int nj = 0; nj < 8; nj++) {
                mx0 = fmaxf(mx0, fmaxf(sacc[nj][0], sacc[nj][1]));
                mx1 = fmaxf(mx1, fmaxf(sacc[nj][2], sacc[nj][3]));
            }
            mx0 = fmaxf(mx0, __shfl_xor_sync(0xffffffffu, mx0, 1));
            mx0 = fmaxf(mx0, __shfl_xor_sync(0xffffffffu, mx0, 2));
            mx1 = fmaxf(mx1, __shfl_xor_sync(0xffffffffu, mx1, 1));
            mx1 = fmaxf(mx1, __shfl_xor_sync(0xffffffffu, mx1, 2));
            float mn0 = fmaxf(m0, mx0), mn1 = fmaxf(m1, mx1);
            float sc0 = __expf(m0 - mn0), sc1 = __expf(m1 - mn1);
            l0 *= sc0; l1 *= sc1;
            #pragma unroll
            for (int nj = 0; nj < 8; nj++) {
                o[nj][0] *= sc0; o[nj][1] *= sc0;
                o[nj][2] *= sc1; o[nj][3] *= sc1;
            }
            #pragma unroll
            for (int nj = 0; nj < 8; nj++) {
                sacc[nj][0] = __expf(sacc[nj][0] - mn0); l0 += sacc[nj][0];
                sacc[nj][1] = __expf(sacc[nj][1] - mn0); l0 += sacc[nj][1];
                sacc[nj][2] = __expf(sacc[nj][2] - mn1); l1 += sacc[nj][2];
                sacc[nj][3] = __expf(sacc[nj][3] - mn1); l1 += sacc[nj][3];
            }
            m0 = mn0; m1 = mn1;

            uint32_t pah[4][4], pal[4][4];
            #pragma unroll
            for (int ks = 0; ks < 4; ks++) {
                pack_hl(sacc[2*ks][0],   sacc[2*ks][1],   pah[ks][0], pal[ks][0]);
                pack_hl(sacc[2*ks][2],   sacc[2*ks][3],   pah[ks][1], pal[ks][1]);
                pack_hl(sacc[2*ks+1][0], sacc[2*ks+1][1], pah[ks][2], pal[ks][2]);
                pack_hl(sacc[2*ks+1][2], sacc[2*ks+1][3], pah[ks][3], pal[ks][3]);
            }

            uint32_t vStage = stage + 8192;
            #pragma unroll
            for (int ks = 0; ks < 4; ks++) {
                #pragma unroll
                for (int nq = 0; nq < 4; nq++) {
                    uint32_t vh4[4];
                    ldm_x4_t(vh4, vStage + swz((uint32_t)((ks*16 + vRow) * 128 + nq*32 + vCb)));
                    mma16816(o[2*nq],   pah[ks], &vh4[0]);
                    mma16816(o[2*nq+1], pah[ks], &vh4[2]);
                    mma16816(o[2*nq],   pal[ks], &vh4[0]);
                    mma16816(o[2*nq+1], pal[ks], &vh4[2]);
                }
            }
        }

        __syncthreads();
        if (kt + 2 < nT) load_kv(sb + 32768 + (kt & 1) * 16384, bh, kt + 2, tid);
        cp_commit();
    }
    cp_wait0();

    l0 += __shfl_xor_sync(0xffffffffu, l0, 1);
    l0 += __shfl_xor_sync(0xffffffffu, l0, 2);
    l1 += __shfl_xor_sync(0xffffffffu, l1, 1);
    l1 += __shfl_xor_sync(0xffffffffu, l1, 2);
    float inv0 = 1.f / l0, inv1 = 1.f / l1;

    int b = bh >> 4, h = bh & 15;
    int row0 = qBase + w * 16 + (l >> 2);
    #pragma unroll
    for (int half = 0; half < 2; half++) {
        int row = row0 + half * 8;
        float inv = half ? inv1 : inv0;
        #pragma unroll
        for (int nj = 0; nj < 8; nj++) {
            int col = h * 64 + nj * 8 + (l & 3) * 2;
            float v0 = o[nj][half * 2 + 0] * inv;
            float v1 = o[nj][half * 2 + 1] * inv;
            uint32_t hh, ll;
            pack_hl(v0, v1, hh, ll);
            size_t gi = (size_t)(b * Sq + row) * Dm + col;
            *(uint32_t*)&g_ah[gi] = hh;
            *(uint32_t*)&g_al[gi] = ll;
        }
    }
}

// ---------------------------------------------------------------------------
extern "C" void kernel_launch(void* const* d_in, const int* in_sizes, int n_in,
                              void* d_out, int out_size)
{
    (void)in_sizes; (void)n_in; (void)out_size;
    const float* x  = (const float*)d_in[0];
    const float* w1 = (const float*)d_in[1];
    const float* b1 = (const float*)d_in[2];
    const float* w2 = (const float*)d_in[3];
    const float* b2 = (const float*)d_in[4];
    float* out = (float*)d_out;

    cudaFuncSetAttribute(tgemm<1>, cudaFuncAttributeMaxDynamicSharedMemorySize, SMEM_TG);
    cudaFuncSetAttribute(tgemm<0>, cudaFuncAttributeMaxDynamicSharedMemorySize, SMEM_TG);
    cudaFuncSetAttribute(flash_mma, cudaFuncAttributeMaxDynamicSharedMemorySize, FL_SMEM);

    split_k<<<4096, 256>>>(x, 4096 * 1024);
    tsplit_k<1><<<dim3(3072 / 32, 1024 / 32), dim3(32, 8)>>>(w1);
    tsplit_k<2><<<dim3(1024 / 32, 1024 / 32), dim3(32, 8)>>>(w2);

    tgemm<1><<<dim3(3072 / 128, 4096 / 256), 256, SMEM_TG>>>(b1, nullptr);
    flash_mma<<<512, 256, FL_SMEM>>>();
    tgemm<0><<<dim3(1024 / 128, 4096 / 256), 256, SMEM_TG>>>(b2, out);
}

// round 11
// speedup vs baseline: 1.3188x; 1.0022x over previous
#include <cuda_runtime.h>
#include <cuda_fp16.h>
#include <cstdint>
#include <math.h>

#define Bc 4
#define Sq 1024
#define Dm 1024
#define Hh 16
#define DHd 64

// ---------------- device scratch (allocation-free rule) ----------------
static constexpr size_t NNqkv = (size_t)Bc * Hh * Sq * DHd;
__device__ __half g_Qh[NNqkv], g_Ql[NNqkv];   // Q split hi/lo, pre-scaled by 1/8
__device__ __half g_Kx[NNqkv];                // K single fp16
__device__ __half g_Vx[NNqkv];                // V single fp16

__device__ __half g_xh[4096*1024], g_xl[4096*1024];   // x split [m][k]
__device__ __half g_w1x[3072*1024];                   // w1^T single [n][k]
__device__ __half g_w2x[1024*1024];                   // w2^T single [n][k]
__device__ __half g_ah[4096*1024], g_al[4096*1024];   // attn out split [m][k]

// ---------------- helpers ----------------
__device__ __forceinline__ uint32_t smem_u32(const void* p) {
    uint32_t a;
    asm("{ .reg .u64 t; cvta.to.shared.u64 t, %1; cvt.u32.u64 %0, t; }" : "=r"(a) : "l"(p));
    return a;
}
__device__ __forceinline__ void cp_async16(uint32_t saddr, const void* gaddr) {
    asm volatile("cp.async.cg.shared.global [%0], [%1], 16;" :: "r"(saddr), "l"(gaddr));
}
__device__ __forceinline__ void cp_commit() { asm volatile("cp.async.commit_group;" ::: "memory"); }
__device__ __forceinline__ void cp_wait1()  { asm volatile("cp.async.wait_group 1;"  ::: "memory"); }
__device__ __forceinline__ void cp_wait2()  { asm volatile("cp.async.wait_group 2;"  ::: "memory"); }
__device__ __forceinline__ void cp_wait0()  { asm volatile("cp.async.wait_group 0;"  ::: "memory"); }

__device__ __forceinline__ void ldm_x4(uint32_t* r, uint32_t addr) {
    asm volatile("ldmatrix.sync.aligned.m8n8.x4.shared.b16 {%0,%1,%2,%3}, [%4];"
        : "=r"(r[0]), "=r"(r[1]), "=r"(r[2]), "=r"(r[3]) : "r"(addr));
}
__device__ __forceinline__ void ldm_x4_t(uint32_t* r, uint32_t addr) {
    asm volatile("ldmatrix.sync.aligned.m8n8.x4.trans.shared.b16 {%0,%1,%2,%3}, [%4];"
        : "=r"(r[0]), "=r"(r[1]), "=r"(r[2]), "=r"(r[3]) : "r"(addr));
}
__device__ __forceinline__ void mma16816(float* d, const uint32_t* a, const uint32_t* b) {
    asm volatile("mma.sync.aligned.m16n8k16.row.col.f32.f16.f16.f32 "
        "{%0,%1,%2,%3}, {%4,%5,%6,%7}, {%8,%9}, {%0,%1,%2,%3};"
        : "+f"(d[0]), "+f"(d[1]), "+f"(d[2]), "+f"(d[3])
        : "r"(a[0]), "r"(a[1]), "r"(a[2]), "r"(a[3]), "r"(b[0]), "r"(b[1]));
}
__device__ __forceinline__ uint32_t swz(uint32_t off)   { return off ^ ((off >> 3) & 0x70); }  // 128B rows
__device__ __forceinline__ uint32_t swz64(uint32_t off) { return off ^ ((off >> 3) & 0x30); }  // 64B rows

__device__ __forceinline__ void pack_hl(float a, float b, uint32_t& hi, uint32_t& lo) {
    __half2 hh = __floats2half2_rn(a, b);
    float ra = a - __half2float(__low2half(hh));
    float rb = b - __half2float(__high2half(hh));
    __half2 ll = __floats2half2_rn(ra, rb);
    hi = *reinterpret_cast<uint32_t*>(&hh);
    lo = *reinterpret_cast<uint32_t*>(&ll);
}
__device__ __forceinline__ uint32_t pack_h2(float a, float b) {
    __half2 hh = __floats2half2_rn(a, b);
    return *reinterpret_cast<uint32_t*>(&hh);
}

// ---------------- split conversion kernels ----------------
__global__ void split_k(const float* __restrict__ in, int n)
{
    int base = (blockIdx.x * blockDim.x + threadIdx.x) * 4;
    if (base >= n) return;
    float4 v = *(const float4*)(in + base);
    uint32_t h0, l0, h1, l1;
    pack_hl(v.x, v.y, h0, l0);
    pack_hl(v.z, v.w, h1, l1);
    *(uint32_t*)(g_xh + base)     = h0;
    *(uint32_t*)(g_xh + base + 2) = h1;
    *(uint32_t*)(g_xl + base)     = l0;
    *(uint32_t*)(g_xl + base + 2) = l1;
}

template<int W>
__global__ void tsplit_k(const float* __restrict__ w)
{
    const int K = 1024;
    const int N = (W == 1) ? 3072 : 1024;
    __half* th = (W == 1) ? g_w1x : g_w2x;
    __shared__ float t[32][33];
    int n0 = blockIdx.x * 32, k0 = blockIdx.y * 32;
    int tx = threadIdx.x, ty = threadIdx.y;
    #pragma unroll
    for (int i = 0; i < 32; i += 8)
        t[ty + i][tx] = w[(size_t)(k0 + ty + i) * N + n0 + tx];
    __syncthreads();
    #pragma unroll
    for (int i = 0; i < 32; i += 8)
        th[(size_t)(n0 + ty + i) * K + k0 + tx] = __float2half_rn(t[tx][ty + i]);
}

// ---------------- HMMA fp16 hi(+lo) GEMM, 256x128 tile, 256 thr, warp 64x64 --
// BK=32, 4 stages. Stage: Ah[0,16K) Al[16K,32K) B[32K,40K). Total 160KB.
static constexpr int TG_STAGES  = 4;
static constexpr int STG_BYTES  = 40960;
static constexpr int SMEM_TG    = TG_STAGES * STG_BYTES;   // 163840

__device__ __forceinline__ void load_stage32(uint32_t sbase,
                                             const __half* Ah, const __half* Al,
                                             const __half* B, bool do_lo,
                                             int mBase, int nBase, int K, int k0, int tid)
{
    const char* gah = (const char*)(Ah + (size_t)mBase * K + k0);
    const char* gal = (const char*)(Al + (size_t)mBase * K + k0);
    #pragma unroll
    for (int i = 0; i < 4; i++) {
        int id = tid + i * 256;          // 0..1023 -> 256 rows x 4 chunks
        int r  = id >> 2;
        int cb = (id & 3) * 16;
        uint32_t off = swz64((uint32_t)(r * 64 + cb));
        cp_async16(sbase + off, gah + (size_t)r * K * 2 + cb);
        if (do_lo)
            cp_async16(sbase + 16384 + off, gal + (size_t)r * K * 2 + cb);
    }
    const char* gb = (const char*)(B + (size_t)nBase * K + k0);
    #pragma unroll
    for (int i = 0; i < 2; i++) {
        int id = tid + i * 256;          // 0..511 -> 128 rows x 4 chunks
        int r  = id >> 2;
        int cb = (id & 3) * 16;
        cp_async16(sbase + 32768 + swz64((uint32_t)(r * 64 + cb)), gb + (size_t)r * K * 2 + cb);
    }
}

template<int MODE>   // 1 = QKV scatter, 0 = proj store fp32
__global__ __launch_bounds__(256, 1) void tgemm(const float* __restrict__ bias,
                                                float* __restrict__ C)
{
    const int K = 1024;
    const int N = (MODE == 1) ? 3072 : 1024;
    const __half* Ah = (MODE == 1) ? g_xh : g_ah;
    const __half* Al = (MODE == 1) ? g_xl : g_al;
    const __half* B  = (MODE == 1) ? g_w1x : g_w2x;

    extern __shared__ char smem[];
    uint32_t sb = smem_u32(smem);
    int tid = threadIdx.x;
    int wid = tid >> 5, l = tid & 31;
    int M0 = (wid & 3) * 64;
    int N0 = (wid >> 2) * 64;
    int mBase = blockIdx.y * 256, nBase = blockIdx.x * 128;
    // lo-correction needed only where the result is kept at high precision:
    // Q columns (n<1024) in QKV mode; everywhere in proj mode.
    bool do_lo = (MODE == 0) || (nBase < 1024);

    float acc[4][8][4];
    #pragma unroll
    for (int mi = 0; mi < 4; mi++)
        #pragma unroll
        for (int nj = 0; nj < 8; nj++)
            #pragma unroll
            for (int k = 0; k < 4; k++) acc[mi][nj][k] = 0.f;

    int aRow = (l & 7) + ((l >> 3) & 1) * 8;
    int aCb  = ((l >> 4) & 1) * 16;
    int bRow = (l & 7) + ((l >> 4) & 1) * 8;
    int bCb  = ((l >> 3) & 1) * 16;

    const int NK = K / 32;   // 32
    #pragma unroll
    for (int s = 0; s < 3; s++) {
        load_stage32(sb + s * STG_BYTES, Ah, Al, B, do_lo, mBase, nBase, K, s * 32, tid);
        cp_commit();
    }

    for (int ko = 0; ko < NK; ko++) {
        cp_wait2();
        __syncthreads();
        uint32_t stage = sb + (ko & (TG_STAGES - 1)) * STG_BYTES;

        #pragma unroll
        for (int ks = 0; ks < 2; ks++) {
            uint32_t rah[4][4], ral[4][4], rb[4][4];
            #pragma unroll
            for (int mi = 0; mi < 4; mi++) {
                uint32_t aoff = swz64((uint32_t)((M0 + mi*16 + aRow) * 64 + ks*32 + aCb));
                ldm_x4(rah[mi], stage + aoff);
                if (do_lo) ldm_x4(ral[mi], stage + 16384 + aoff);
            }
            #pragma unroll
            for (int nq = 0; nq < 4; nq++)
                ldm_x4(rb[nq], stage + 32768 + swz64((uint32_t)((N0 + nq*16 + bRow) * 64 + ks*32 + bCb)));
            #pragma unroll
            for (int mi = 0; mi < 4; mi++)
                #pragma unroll
                for (int nj = 0; nj < 8; nj++) {
                    const uint32_t* bp = &rb[nj >> 1][(nj & 1) * 2];
                    mma16816(acc[mi][nj], rah[mi], bp);
                    if (do_lo) mma16816(acc[mi][nj], ral[mi], bp);
                }
        }
        // issue next stage (writes stage (ko-1)%4, consumed last iter; safe after top sync)
        if (ko + 3 < NK)
            load_stage32(sb + ((ko + 3) & (TG_STAGES - 1)) * STG_BYTES,
                         Ah, Al, B, do_lo, mBase, nBase, K, (ko + 3) * 32, tid);
        cp_commit();   // unconditional: keeps group count aligned with wait_group(2)
    }

    #pragma unroll
    for (int mi = 0; mi < 4; mi++) {
        #pragma unroll
        for (int half = 0; half < 2; half++) {
            int m = mBase + M0 + mi * 16 + (l >> 2) + half * 8;
            #pragma unroll
            for (int nj = 0; nj < 8; nj++) {
                int n = nBase + N0 + nj * 8 + (l & 3) * 2;
                float v0 = acc[mi][nj][half * 2 + 0] + bias[n];
                float v1 = acc[mi][nj][half * 2 + 1] + bias[n + 1];
                if (MODE == 1) {
                    int which = n >> 10;
                    int dc = n & 1023;
                    int h = dc >> 6, dh = dc & 63;
                    int b = m >> 10, s2 = m & 1023;
                    size_t gi = (((size_t)(b * Hh + h)) * Sq + s2) * DHd + dh;
                    if (which == 0) {
                        uint32_t hh, ll;
                        pack_hl(v0 * 0.125f, v1 * 0.125f, hh, ll);
                        *(uint32_t*)&g_Qh[gi] = hh;
                        *(uint32_t*)&g_Ql[gi] = ll;
                    } else if (which == 1) {
                        *(uint32_t*)&g_Kx[gi] = pack_h2(v0, v1);
                    } else {
                        *(uint32_t*)&g_Vx[gi] = pack_h2(v0, v1);
                    }
                } else {
                    C[(size_t)m * N + n]     = v0;
                    C[(size_t)m * N + n + 1] = v1;
                }
            }
        }
    }
}

// ---------------- tensor-core causal flash attention (R8 version) ----------------
// SMEM: Qh[0,16K) Ql[16K,32K); stages at 32K: {K 8K, V 8K} x 2. Total 64K.
static constexpr int FL_SMEM = 32768 + 2 * 16384;

__device__ __forceinline__ void load_kv(uint32_t sdst, int bh, int kt, int tid)
{
    const __half* srcs[2] = {g_Kx, g_Vx};
    size_t base = (size_t)bh * Sq * DHd + (size_t)kt * 64 * DHd;
    #pragma unroll
    for (int t = 0; t < 2; t++) {
        const char* g = (const char*)(srcs[t] + base);
        uint32_t sd = sdst + t * 8192;
        #pragma unroll
        for (int i = 0; i < 2; i++) {
            int id = tid + i * 256;
            int r  = id >> 3;
            int cb = (id & 7) * 16;
            cp_async16(sd + swz((uint32_t)(r * 128 + cb)), g + (size_t)r * 128 + cb);
        }
    }
}

__global__ __launch_bounds__(256) void flash_mma()
{
    extern __shared__ char smem[];
    uint32_t sb = smem_u32(smem);
    int tid = threadIdx.x;
    int w = tid >> 5, l = tid & 31;

    int qc = 7 - (blockIdx.x >> 6);
    int bh = blockIdx.x & 63;
    int qBase = qc * 128;

    {
        const char* gh = (const char*)(g_Qh + (size_t)bh * Sq * DHd + (size_t)qBase * DHd);
        const char* gl = (const char*)(g_Ql + (size_t)bh * Sq * DHd + (size_t)qBase * DHd);
        #pragma unroll
        for (int i = 0; i < 4; i++) {
            int id = tid + i * 256;
            int r  = id >> 3;
            int cb = (id & 7) * 16;
            cp_async16(sb +         swz((uint32_t)(r * 128 + cb)), gh + (size_t)r * 128 + cb);
            cp_async16(sb + 16384 + swz((uint32_t)(r * 128 + cb)), gl + (size_t)r * 128 + cb);
        }
    }
    load_kv(sb + 32768, bh, 0, tid);
    cp_commit();
    int nT = (qc + 1) * 2;
    load_kv(sb + 32768 + 16384, bh, 1, tid);
    cp_commit();

    cp_wait1();
    __syncthreads();

    int aRow = (l & 7) + ((l >> 3) & 1) * 8;
    int aCb  = ((l >> 4) & 1) * 16;
    int bRow = (l & 7) + ((l >> 4) & 1) * 8;
    int bCb  = ((l >> 3) & 1) * 16;
    int vRow = (l & 7) + ((l >> 3) & 1) * 8;
    int vCb  = ((l >> 4) & 1) * 16;

    uint32_t qh[4][4], ql[4][4];
    #pragma unroll
    for (int ks = 0; ks < 4; ks++) {
        ldm_x4(qh[ks], sb +         swz((uint32_t)((w*16 + aRow) * 128 + ks*32 + aCb)));
        ldm_x4(ql[ks], sb + 16384 + swz((uint32_t)((w*16 + aRow) * 128 + ks*32 + aCb)));
    }

    float o[8][4];
    #pragma unroll
    for (int nj = 0; nj < 8; nj++)
        #pragma unroll
        for (int k = 0; k < 4; k++) o[nj][k] = 0.f;
    float m0 = -1e30f, m1 = -1e30f, l0 = 0.f, l1 = 0.f;

    for (int kt = 0; kt < nT; kt++) {
        cp_wait1();
        __syncthreads();
        uint32_t stage = sb + 32768 + (kt & 1) * 16384;

        bool skip = (kt * 64 > qBase + w * 16 + 15);
        if (!skip) {
            float sacc[8][4];
            #pragma unroll
            for (int nj = 0; nj < 8; nj++)
                #pragma unroll
                for (int k = 0; k < 4; k++) sacc[nj][k] = 0.f;

            #pragma unroll
            for (int ks = 0; ks < 4; ks++) {
                #pragma unroll
                for (int nq = 0; nq < 4; nq++) {
                    uint32_t kh4[4];
                    ldm_x4(kh4, stage + swz((uint32_t)((nq*16 + bRow) * 128 + ks*32 + bCb)));
                    mma16816(sacc[2*nq],   qh[ks], &kh4[0]);
                    mma16816(sacc[2*nq+1], qh[ks], &kh4[2]);
                    mma16816(sacc[2*nq],   ql[ks], &kh4[0]);
                    mma16816(sacc[2*nq+1], ql[ks], &kh4[2]);
                }
            }

            int r0 = qBase + w * 16 + (l >> 2);
            if (kt * 64 + 63 > r0) {
                int kc = kt * 64 + (l & 3) * 2;
                #pragma unroll
                for (int nj = 0; nj < 8; nj++) {
                    int k0 = kc + nj * 8;
                    if (k0     > r0)     sacc[nj][0] = -1e30f;
                    if (k0 + 1 > r0)     sacc[nj][1] = -1e30f;
                    if (k0     > r0 + 8) sacc[nj][2] = -1e30f;
                    if (k0 + 1 > r0 + 8) sacc[nj][3] = -1e30f;
                }
            }

            float mx0 = -1e30f, mx1 = -1e30f;
            #pragma unroll
            for (int nj = 0; nj < 8; nj++) {
                mx0 = fmaxf(mx0, fmaxf(sacc[nj][0], sacc[nj][1]));
                mx1 = fmaxf(mx1, fmaxf(sacc[nj][2], sacc[nj][3]));
            }
            mx0 = fmaxf(mx0, __shfl_xor_sync(0xffffffffu, mx0, 1));
            mx0 = fmaxf(mx0, __shfl_xor_sync(0xffffffffu, mx0, 2));
            mx1 = fmaxf(mx1, __shfl_xor_sync(0xffffffffu, mx1, 1));
            mx1 = fmaxf(mx1, __shfl_xor_sync(0xffffffffu, mx1, 2));
            float mn0 = fmaxf(m0, mx0), mn1 = fmaxf(m1, mx1);
            float sc0 = __expf(m0 - mn0), sc1 = __expf(m1 - mn1);
            l0 *= sc0; l1 *= sc1;
            #pragma unroll
            for (int nj = 0; nj < 8; nj++) {
                o[nj][0] *= sc0; o[nj][1] *= sc0;
                o[nj][2] *= sc1; o[nj][3] *= sc1;
            }
            #pragma unroll
            for (int nj = 0; nj < 8; nj++) {
                sacc[nj][0] = __expf(sacc[nj][0] - mn0); l0 += sacc[nj][0];
                sacc[nj][1] = __expf(sacc[nj][1] - mn0); l0 += sacc[nj][1];
                sacc[nj][2] = __expf(sacc[nj][2] - mn1); l1 += sacc[nj][2];
                sacc[nj][3] = __expf(sacc[nj][3] - mn1); l1 += sacc[nj][3];
            }
            m0 = mn0; m1 = mn1;

            uint32_t pah[4][4], pal[4][4];
            #pragma unroll
            for (int ks = 0; ks < 4; ks++) {
                pack_hl(sacc[2*ks][0],   sacc[2*ks][1],   pah[ks][0], pal[ks][0]);
                pack_hl(sacc[2*ks][2],   sacc[2*ks][3],   pah[ks][1], pal[ks][1]);
                pack_hl(sacc[2*ks+1][0], sacc[2*ks+1][1], pah[ks][2], pal[ks][2]);
                pack_hl(sacc[2*ks+1][2], sacc[2*ks+1][3], pah[ks][3], pal[ks][3]);
            }

            uint32_t vStage = stage + 8192;
            #pragma unroll
            for (int ks = 0; ks < 4; ks++) {
                #pragma unroll
                for (int nq = 0; nq < 4; nq++) {
                    uint32_t vh4[4];
                    ldm_x4_t(vh4, vStage + swz((uint32_t)((ks*16 + vRow) * 128 + nq*32 + vCb)));
                    mma16816(o[2*nq],   pah[ks], &vh4[0]);
                    mma16816(o[2*nq+1], pah[ks], &vh4[2]);
                    mma16816(o[2*nq],   pal[ks], &vh4[0]);
                    mma16816(o[2*nq+1], pal[ks], &vh4[2]);
                }
            }
        }

        __syncthreads();
        if (kt + 2 < nT) load_kv(sb + 32768 + (kt & 1) * 16384, bh, kt + 2, tid);
        cp_commit();
    }
    cp_wait0();

    l0 += __shfl_xor_sync(0xffffffffu, l0, 1);
    l0 += __shfl_xor_sync(0xffffffffu, l0, 2);
    l1 += __shfl_xor_sync(0xffffffffu, l1, 1);
    l1 += __shfl_xor_sync(0xffffffffu, l1, 2);
    float inv0 = 1.f / l0, inv1 = 1.f / l1;

    int b = bh >> 4, h = bh & 15;
    int row0 = qBase + w * 16 + (l >> 2);
    #pragma unroll
    for (int half = 0; half < 2; half++) {
        int row = row0 + half * 8;
        float inv = half ? inv1 : inv0;
        #pragma unroll
        for (int nj = 0; nj < 8; nj++) {
            int col = h * 64 + nj * 8 + (l & 3) * 2;
            float v0 = o[nj][half * 2 + 0] * inv;
            float v1 = o[nj][half * 2 + 1] * inv;
            uint32_t hh, ll;
            pack_hl(v0, v1, hh, ll);
            size_t gi = (size_t)(b * Sq + row) * Dm + col;
            *(uint32_t*)&g_ah[gi] = hh;
            *(uint32_t*)&g_al[gi] = ll;
        }
    }
}

// ---------------------------------------------------------------------------
extern "C" void kernel_launch(void* const* d_in, const int* in_sizes, int n_in,
                              void* d_out, int out_size)
{
    (void)in_sizes; (void)n_in; (void)out_size;
    const float* x  = (const float*)d_in[0];
    const float* w1 = (const float*)d_in[1];
    const float* b1 = (const float*)d_in[2];
    const float* w2 = (const float*)d_in[3];
    const float* b2 = (const float*)d_in[4];
    float* out = (float*)d_out;

    cudaFuncSetAttribute(tgemm<1>, cudaFuncAttributeMaxDynamicSharedMemorySize, SMEM_TG);
    cudaFuncSetAttribute(tgemm<0>, cudaFuncAttributeMaxDynamicSharedMemorySize, SMEM_TG);
    cudaFuncSetAttribute(flash_mma, cudaFuncAttributeMaxDynamicSharedMemorySize, FL_SMEM);

    split_k<<<4096, 256>>>(x, 4096 * 1024);
    tsplit_k<1><<<dim3(3072 / 32, 1024 / 32), dim3(32, 8)>>>(w1);
    tsplit_k<2><<<dim3(1024 / 32, 1024 / 32), dim3(32, 8)>>>(w2);

    tgemm<1><<<dim3(3072 / 128, 4096 / 256), 256, SMEM_TG>>>(b1, nullptr);
    flash_mma<<<512, 256, FL_SMEM>>>();
    tgemm<0><<<dim3(1024 / 128, 4096 / 256), 256, SMEM_TG>>>(b2, out);
}

// round 12
// speedup vs baseline: 1.3354x; 1.0126x over previous
#include <cuda_runtime.h>
#include <cuda_fp16.h>
#include <cstdint>
#include <math.h>

#define Bc 4
#define Sq 1024
#define Dm 1024
#define Hh 16
#define DHd 64

// ---------------- device scratch (allocation-free rule) ----------------
static constexpr size_t NNqkv = (size_t)Bc * Hh * Sq * DHd;
__device__ __half g_Qh[NNqkv], g_Ql[NNqkv];   // Q split hi/lo, pre-scaled by 1/8
__device__ __half g_Kx[NNqkv];                // K single fp16
__device__ __half g_Vx[NNqkv];                // V single fp16

__device__ __half g_xh[4096*1024], g_xl[4096*1024];   // x split [m][k]
__device__ __half g_w1x[3072*1024];                   // w1^T single [n][k]
__device__ __half g_w2x[1024*1024];                   // w2^T single [n][k]
__device__ __half g_ah[4096*1024], g_al[4096*1024];   // attn out split [m][k]

// ---------------- helpers ----------------
__device__ __forceinline__ uint32_t smem_u32(const void* p) {
    uint32_t a;
    asm("{ .reg .u64 t; cvta.to.shared.u64 t, %1; cvt.u32.u64 %0, t; }" : "=r"(a) : "l"(p));
    return a;
}
__device__ __forceinline__ void cp_async16(uint32_t saddr, const void* gaddr) {
    asm volatile("cp.async.cg.shared.global [%0], [%1], 16;" :: "r"(saddr), "l"(gaddr));
}
__device__ __forceinline__ void cp_commit() { asm volatile("cp.async.commit_group;" ::: "memory"); }
__device__ __forceinline__ void cp_wait1()  { asm volatile("cp.async.wait_group 1;"  ::: "memory"); }
__device__ __forceinline__ void cp_wait0()  { asm volatile("cp.async.wait_group 0;"  ::: "memory"); }

__device__ __forceinline__ void ldm_x4(uint32_t* r, uint32_t addr) {
    asm volatile("ldmatrix.sync.aligned.m8n8.x4.shared.b16 {%0,%1,%2,%3}, [%4];"
        : "=r"(r[0]), "=r"(r[1]), "=r"(r[2]), "=r"(r[3]) : "r"(addr));
}
__device__ __forceinline__ void ldm_x4_t(uint32_t* r, uint32_t addr) {
    asm volatile("ldmatrix.sync.aligned.m8n8.x4.trans.shared.b16 {%0,%1,%2,%3}, [%4];"
        : "=r"(r[0]), "=r"(r[1]), "=r"(r[2]), "=r"(r[3]) : "r"(addr));
}
__device__ __forceinline__ void mma16816(float* d, const uint32_t* a, const uint32_t* b) {
    asm volatile("mma.sync.aligned.m16n8k16.row.col.f32.f16.f16.f32 "
        "{%0,%1,%2,%3}, {%4,%5,%6,%7}, {%8,%9}, {%0,%1,%2,%3};"
        : "+f"(d[0]), "+f"(d[1]), "+f"(d[2]), "+f"(d[3])
        : "r"(a[0]), "r"(a[1]), "r"(a[2]), "r"(a[3]), "r"(b[0]), "r"(b[1]));
}
__device__ __forceinline__ uint32_t swz(uint32_t off) { return off ^ ((off >> 3) & 0x70); }

__device__ __forceinline__ void pack_hl(float a, float b, uint32_t& hi, uint32_t& lo) {
    __half2 hh = __floats2half2_rn(a, b);
    float ra = a - __half2float(__low2half(hh));
    float rb = b - __half2float(__high2half(hh));
    __half2 ll = __floats2half2_rn(ra, rb);
    hi = *reinterpret_cast<uint32_t*>(&hh);
    lo = *reinterpret_cast<uint32_t*>(&ll);
}
__device__ __forceinline__ uint32_t pack_h2(float a, float b) {
    __half2 hh = __floats2half2_rn(a, b);
    return *reinterpret_cast<uint32_t*>(&hh);
}

// ---------------- split conversion kernels ----------------
__global__ void split_k(const float* __restrict__ in, int n)
{
    int base = (blockIdx.x * blockDim.x + threadIdx.x) * 4;
    if (base >= n) return;
    float4 v = *(const float4*)(in + base);
    uint32_t h0, l0, h1, l1;
    pack_hl(v.x, v.y, h0, l0);
    pack_hl(v.z, v.w, h1, l1);
    *(uint32_t*)(g_xh + base)     = h0;
    *(uint32_t*)(g_xh + base + 2) = h1;
    *(uint32_t*)(g_xl + base)     = l0;
    *(uint32_t*)(g_xl + base + 2) = l1;
}

template<int W>
__global__ void tsplit_k(const float* __restrict__ w)
{
    const int K = 1024;
    const int N = (W == 1) ? 3072 : 1024;
    __half* th = (W == 1) ? g_w1x : g_w2x;
    __shared__ float t[32][33];
    int n0 = blockIdx.x * 32, k0 = blockIdx.y * 32;
    int tx = threadIdx.x, ty = threadIdx.y;
    #pragma unroll
    for (int i = 0; i < 32; i += 8)
        t[ty + i][tx] = w[(size_t)(k0 + ty + i) * N + n0 + tx];
    __syncthreads();
    #pragma unroll
    for (int i = 0; i < 32; i += 8)
        th[(size_t)(n0 + ty + i) * K + k0 + tx] = __float2half_rn(t[tx][ty + i]);
}

// ---------------- HMMA fp16 hi(+lo) GEMM, 256x128 tile, 256 thr, warp 64x64 --
// BK=64, 2 stages. Stage: Ah[0,32K) Al[32K,64K) B[64K,80K); 2 stages = 160KB.
static constexpr int ST2_BYTES   = 81920;
static constexpr int SMEM_TOTAL2 = 2 * ST2_BYTES;

__device__ __forceinline__ void load_stage2(uint32_t sbase,
                                            const __half* Ah, const __half* Al,
                                            const __half* B, bool do_lo,
                                            int mBase, int nBase, int K, int k0, int tid)
{
    const char* gah = (const char*)(Ah + (size_t)mBase * K + k0);
    const char* gal = (const char*)(Al + (size_t)mBase * K + k0);
    #pragma unroll
    for (int i = 0; i < 8; i++) {
        int id = tid + i * 256;
        int r  = id >> 3;
        int cb = (id & 7) * 16;
        uint32_t off = swz((uint32_t)(r * 128 + cb));
        cp_async16(sbase + off, gah + (size_t)r * K * 2 + cb);
        if (do_lo)
            cp_async16(sbase + 32768 + off, gal + (size_t)r * K * 2 + cb);
    }
    const char* gb = (const char*)(B + (size_t)nBase * K + k0);
    #pragma unroll
    for (int i = 0; i < 4; i++) {
        int id = tid + i * 256;
        int r  = id >> 3;
        int cb = (id & 7) * 16;
        cp_async16(sbase + 65536 + swz((uint32_t)(r * 128 + cb)), gb + (size_t)r * K * 2 + cb);
    }
}

template<int MODE>   // 1 = QKV scatter, 0 = proj store fp32
__global__ __launch_bounds__(256, 1) void tgemm(const float* __restrict__ bias,
                                                float* __restrict__ C)
{
    const int K = 1024;
    const int N = (MODE == 1) ? 3072 : 1024;
    const __half* Ah = (MODE == 1) ? g_xh : g_ah;
    const __half* Al = (MODE == 1) ? g_xl : g_al;
    const __half* B  = (MODE == 1) ? g_w1x : g_w2x;

    extern __shared__ char smem[];
    uint32_t sb = smem_u32(smem);
    int tid = threadIdx.x;
    int wid = tid >> 5, l = tid & 31;
    int M0 = (wid & 3) * 64;
    int N0 = (wid >> 2) * 64;
    int mBase = blockIdx.y * 256, nBase = blockIdx.x * 128;
    // lo-correction only where result is kept high-precision:
    // Q columns (n<1024) in QKV mode; everywhere in proj mode.
    bool do_lo = (MODE == 0) || (nBase < 1024);

    float acc[4][8][4];
    #pragma unroll
    for (int mi = 0; mi < 4; mi++)
        #pragma unroll
        for (int nj = 0; nj < 8; nj++)
            #pragma unroll
            for (int k = 0; k < 4; k++) acc[mi][nj][k] = 0.f;

    int aRow = (l & 7) + ((l >> 3) & 1) * 8;
    int aCb  = ((l >> 4) & 1) * 16;
    int bRow = (l & 7) + ((l >> 4) & 1) * 8;
    int bCb  = ((l >> 3) & 1) * 16;

    const int NK = K / 64;
    load_stage2(sb,             Ah, Al, B, do_lo, mBase, nBase, K, 0,  tid); cp_commit();
    load_stage2(sb + ST2_BYTES, Ah, Al, B, do_lo, mBase, nBase, K, 64, tid); cp_commit();

    for (int ko = 0; ko < NK; ko++) {
        cp_wait1();
        __syncthreads();
        uint32_t stage = sb + (ko & 1) * ST2_BYTES;

        #pragma unroll
        for (int ks = 0; ks < 4; ks++) {
            uint32_t rah[4][4], ral[4][4], rb[4][4];
            #pragma unroll
            for (int mi = 0; mi < 4; mi++) {
                uint32_t aoff = swz((uint32_t)((M0 + mi*16 + aRow) * 128 + ks*32 + aCb));
                ldm_x4(rah[mi], stage + aoff);
                if (do_lo) ldm_x4(ral[mi], stage + 32768 + aoff);
            }
            #pragma unroll
            for (int nq = 0; nq < 4; nq++)
                ldm_x4(rb[nq], stage + 65536 + swz((uint32_t)((N0 + nq*16 + bRow) * 128 + ks*32 + bCb)));
            #pragma unroll
            for (int mi = 0; mi < 4; mi++)
                #pragma unroll
                for (int nj = 0; nj < 8; nj++) {
                    const uint32_t* bp = &rb[nj >> 1][(nj & 1) * 2];
                    mma16816(acc[mi][nj], rah[mi], bp);
                    if (do_lo) mma16816(acc[mi][nj], ral[mi], bp);
                }
        }
        __syncthreads();
        if (ko + 2 < NK)
            load_stage2(sb + (ko & 1) * ST2_BYTES, Ah, Al, B, do_lo, mBase, nBase, K, (ko + 2) * 64, tid);
        cp_commit();
    }

    #pragma unroll
    for (int mi = 0; mi < 4; mi++) {
        #pragma unroll
        for (int half = 0; half < 2; half++) {
            int m = mBase + M0 + mi * 16 + (l >> 2) + half * 8;
            #pragma unroll
            for (int nj = 0; nj < 8; nj++) {
                int n = nBase + N0 + nj * 8 + (l & 3) * 2;
                float v0 = acc[mi][nj][half * 2 + 0] + bias[n];
                float v1 = acc[mi][nj][half * 2 + 1] + bias[n + 1];
                if (MODE == 1) {
                    int which = n >> 10;
                    int dc = n & 1023;
                    int h = dc >> 6, dh = dc & 63;
                    int b = m >> 10, s2 = m & 1023;
                    size_t gi = (((size_t)(b * Hh + h)) * Sq + s2) * DHd + dh;
                    if (which == 0) {
                        uint32_t hh, ll;
                        pack_hl(v0 * 0.125f, v1 * 0.125f, hh, ll);
                        *(uint32_t*)&g_Qh[gi] = hh;
                        *(uint32_t*)&g_Ql[gi] = ll;
                    } else if (which == 1) {
                        *(uint32_t*)&g_Kx[gi] = pack_h2(v0, v1);
                    } else {
                        *(uint32_t*)&g_Vx[gi] = pack_h2(v0, v1);
                    }
                } else {
                    C[(size_t)m * N + n]     = v0;
                    C[(size_t)m * N + n + 1] = v1;
                }
            }
        }
    }
}

// ---------------- tensor-core causal flash attention (R8 version) ----------------
// SMEM: Qh[0,16K) Ql[16K,32K); stages at 32K: {K 8K, V 8K} x 2. Total 64K.
static constexpr int FL_SMEM = 32768 + 2 * 16384;

__device__ __forceinline__ void load_kv(uint32_t sdst, int bh, int kt, int tid)
{
    const __half* srcs[2] = {g_Kx, g_Vx};
    size_t base = (size_t)bh * Sq * DHd + (size_t)kt * 64 * DHd;
    #pragma unroll
    for (int t = 0; t < 2; t++) {
        const char* g = (const char*)(srcs[t] + base);
        uint32_t sd = sdst + t * 8192;
        #pragma unroll
        for (int i = 0; i < 2; i++) {
            int id = tid + i * 256;
            int r  = id >> 3;
            int cb = (id & 7) * 16;
            cp_async16(sd + swz((uint32_t)(r * 128 + cb)), g + (size_t)r * 128 + cb);
        }
    }
}

__global__ __launch_bounds__(256) void flash_mma()
{
    extern __shared__ char smem[];
    uint32_t sb = smem_u32(smem);
    int tid = threadIdx.x;
    int w = tid >> 5, l = tid & 31;

    int qc = 7 - (blockIdx.x >> 6);
    int bh = blockIdx.x & 63;
    int qBase = qc * 128;

    {
        const char* gh = (const char*)(g_Qh + (size_t)bh * Sq * DHd + (size_t)qBase * DHd);
        const char* gl = (const char*)(g_Ql + (size_t)bh * Sq * DHd + (size_t)qBase * DHd);
        #pragma unroll
        for (int i = 0; i < 4; i++) {
            int id = tid + i * 256;
            int r  = id >> 3;
            int cb = (id & 7) * 16;
            cp_async16(sb +         swz((uint32_t)(r * 128 + cb)), gh + (size_t)r * 128 + cb);
            cp_async16(sb + 16384 + swz((uint32_t)(r * 128 + cb)), gl + (size_t)r * 128 + cb);
        }
    }
    load_kv(sb + 32768, bh, 0, tid);
    cp_commit();
    int nT = (qc + 1) * 2;
    load_kv(sb + 32768 + 16384, bh, 1, tid);
    cp_commit();

    cp_wait1();
    __syncthreads();

    int aRow = (l & 7) + ((l >> 3) & 1) * 8;
    int aCb  = ((l >> 4) & 1) * 16;
    int bRow = (l & 7) + ((l >> 4) & 1) * 8;
    int bCb  = ((l >> 3) & 1) * 16;
    int vRow = (l & 7) + ((l >> 3) & 1) * 8;
    int vCb  = ((l >> 4) & 1) * 16;

    uint32_t qh[4][4], ql[4][4];
    #pragma unroll
    for (int ks = 0; ks < 4; ks++) {
        ldm_x4(qh[ks], sb +         swz((uint32_t)((w*16 + aRow) * 128 + ks*32 + aCb)));
        ldm_x4(ql[ks], sb + 16384 + swz((uint32_t)((w*16 + aRow) * 128 + ks*32 + aCb)));
    }

    float o[8][4];
    #pragma unroll
    for (int nj = 0; nj < 8; nj++)
        #pragma unroll
        for (int k = 0; k < 4; k++) o[nj][k] = 0.f;
    float m0 = -1e30f, m1 = -1e30f, l0 = 0.f, l1 = 0.f;

    for (int kt = 0; kt < nT; kt++) {
        cp_wait1();
        __syncthreads();
        uint32_t stage = sb + 32768 + (kt & 1) * 16384;

        bool skip = (kt * 64 > qBase + w * 16 + 15);
        if (!skip) {
            float sacc[8][4];
            #pragma unroll
            for (int nj = 0; nj < 8; nj++)
                #pragma unroll
                for (int k = 0; k < 4; k++) sacc[nj][k] = 0.f;

            #pragma unroll
            for (int ks = 0; ks < 4; ks++) {
                #pragma unroll
                for (int nq = 0; nq < 4; nq++) {
                    uint32_t kh4[4];
                    ldm_x4(kh4, stage + swz((uint32_t)((nq*16 + bRow) * 128 + ks*32 + bCb)));
                    mma16816(sacc[2*nq],   qh[ks], &kh4[0]);
                    mma16816(sacc[2*nq+1], qh[ks], &kh4[2]);
                    mma16816(sacc[2*nq],   ql[ks], &kh4[0]);
                    mma16816(sacc[2*nq+1], ql[ks], &kh4[2]);
                }
            }

            int r0 = qBase + w * 16 + (l >> 2);
            if (kt * 64 + 63 > r0) {
                int kc = kt * 64 + (l & 3) * 2;
                #pragma unroll
                for (int nj = 0; nj < 8; nj++) {
                    int k0 = kc + nj * 8;
                    if (k0     > r0)     sacc[nj][0] = -1e30f;
                    if (k0 + 1 > r0)     sacc[nj][1] = -1e30f;
                    if (k0     > r0 + 8) sacc[nj][2] = -1e30f;
                    if (k0 + 1 > r0 + 8) sacc[nj][3] = -1e30f;
                }
            }

            float mx0 = -1e30f, mx1 = -1e30f;
            #pragma unroll
            for (int nj = 0; nj < 8; nj++) {
                mx0 = fmaxf(mx0, fmaxf(sacc[nj][0], sacc[nj][1]));
                mx1 = fmaxf(mx1, fmaxf(sacc[nj][2], sacc[nj][3]));
            }
            mx0 = fmaxf(mx0, __shfl_xor_sync(0xffffffffu, mx0, 1));
            mx0 = fmaxf(mx0, __shfl_xor_sync(0xffffffffu, mx0, 2));
            mx1 = fmaxf(mx1, __shfl_xor_sync(0xffffffffu, mx1, 1));
            mx1 = fmaxf(mx1, __shfl_xor_sync(0xffffffffu, mx1, 2));
            float mn0 = fmaxf(m0, mx0), mn1 = fmaxf(m1, mx1);
            float sc0 = __expf(m0 - mn0), sc1 = __expf(m1 - mn1);
            l0 *= sc0; l1 *= sc1;
            #pragma unroll
            for (int nj = 0; nj < 8; nj++) {
                o[nj][0] *= sc0; o[nj][1] *= sc0;
                o[nj][2] *= sc1; o[nj][3] *= sc1;
            }
            #pragma unroll
            for (int nj = 0; nj < 8; nj++) {
                sacc[nj][0] = __expf(sacc[nj][0] - mn0); l0 += sacc[nj][0];
                sacc[nj][1] = __expf(sacc[nj][1] - mn0); l0 += sacc[nj][1];
                sacc[nj][2] = __expf(sacc[nj][2] - mn1); l1 += sacc[nj][2];
                sacc[nj][3] = __expf(sacc[nj][3] - mn1); l1 += sacc[nj][3];
            }
            m0 = mn0; m1 = mn1;

            uint32_t pah[4][4], pal[4][4];
            #pragma unroll
            for (int ks = 0; ks < 4; ks++) {
                pack_hl(sacc[2*ks][0],   sacc[2*ks][1],   pah[ks][0], pal[ks][0]);
                pack_hl(sacc[2*ks][2],   sacc[2*ks][3],   pah[ks][1], pal[ks][1]);
                pack_hl(sacc[2*ks+1][0], sacc[2*ks+1][1], pah[ks][2], pal[ks][2]);
                pack_hl(sacc[2*ks+1][2], sacc[2*ks+1][3], pah[ks][3], pal[ks][3]);
            }

            uint32_t vStage = stage + 8192;
            #pragma unroll
            for (int ks = 0; ks < 4; ks++) {
                #pragma unroll
                for (int nq = 0; nq < 4; nq++) {
                    uint32_t vh4[4];
                    ldm_x4_t(vh4, vStage + swz((uint32_t)((ks*16 + vRow) * 128 + nq*32 + vCb)));
                    mma16816(o[2*nq],   pah[ks], &vh4[0]);
                    mma16816(o[2*nq+1], pah[ks], &vh4[2]);
                    mma16816(o[2*nq],   pal[ks], &vh4[0]);
                    mma16816(o[2*nq+1], pal[ks], &vh4[2]);
                }
            }
        }

        __syncthreads();
        if (kt + 2 < nT) load_kv(sb + 32768 + (kt & 1) * 16384, bh, kt + 2, tid);
        cp_commit();
    }
    cp_wait0();

    l0 += __shfl_xor_sync(0xffffffffu, l0, 1);
    l0 += __shfl_xor_sync(0xffffffffu, l0, 2);
    l1 += __shfl_xor_sync(0xffffffffu, l1, 1);
    l1 += __shfl_xor_sync(0xffffffffu, l1, 2);
    float inv0 = 1.f / l0, inv1 = 1.f / l1;

    int b = bh >> 4, h = bh & 15;
    int row0 = qBase + w * 16 + (l >> 2);
    #pragma unroll
    for (int half = 0; half < 2; half++) {
        int row = row0 + half * 8;
        float inv = half ? inv1 : inv0;
        #pragma unroll
        for (int nj = 0; nj < 8; nj++) {
            int col = h * 64 + nj * 8 + (l & 3) * 2;
            float v0 = o[nj][half * 2 + 0] * inv;
            float v1 = o[nj][half * 2 + 1] * inv;
            uint32_t hh, ll;
            pack_hl(v0, v1, hh, ll);
            size_t gi = (size_t)(b * Sq + row) * Dm + col;
            *(uint32_t*)&g_ah[gi] = hh;
            *(uint32_t*)&g_al[gi] = ll;
        }
    }
}

// ---------------------------------------------------------------------------
extern "C" void kernel_launch(void* const* d_in, const int* in_sizes, int n_in,
                              void* d_out, int out_size)
{
    (void)in_sizes; (void)n_in; (void)out_size;
    const float* x  = (const float*)d_in[0];
    const float* w1 = (const float*)d_in[1];
    const float* b1 = (const float*)d_in[2];
    const float* w2 = (const float*)d_in[3];
    const float* b2 = (const float*)d_in[4];
    float* out = (float*)d_out;

    cudaFuncSetAttribute(tgemm<1>, cudaFuncAttributeMaxDynamicSharedMemorySize, SMEM_TOTAL2);
    cudaFuncSetAttribute(tgemm<0>, cudaFuncAttributeMaxDynamicSharedMemorySize, SMEM_TOTAL2);
    cudaFuncSetAttribute(flash_mma, cudaFuncAttributeMaxDynamicSharedMemorySize, FL_SMEM);

    split_k<<<4096, 256>>>(x, 4096 * 1024);
    tsplit_k<1><<<dim3(3072 / 32, 1024 / 32), dim3(32, 8)>>>(w1);
    tsplit_k<2><<<dim3(1024 / 32, 1024 / 32), dim3(32, 8)>>>(w2);

    tgemm<1><<<dim3(3072 / 128, 4096 / 256), 256, SMEM_TOTAL2>>>(b1, nullptr);
    flash_mma<<<512, 256, FL_SMEM>>>();
    tgemm<0><<<dim3(1024 / 128, 4096 / 256), 256, SMEM_TOTAL2>>>(b2, out);
}